// round 5
// baseline (speedup 1.0000x reference)
#include <cuda_runtime.h>
#include <cuda_fp16.h>

// Problem constants (BOWRegressionMulti: T=200, B=1024, V=50000, L=512, PAD=1)
#define T_TOK 200
#define B_SZ  1024
#define V_SZ  50000
#define L_SZ  512
#define PAD_TOK 1
#define V_WORDS ((V_SZ + 31) / 32)

// Scratch (static device globals — no allocs):
__device__ __half   g_Wt_h[(size_t)V_SZ * L_SZ];       // 51.2 MB transposed fp16 weights
__device__ unsigned g_toks[B_SZ][T_TOK];               // per-row deduped BYTE offsets (v*1024)
__device__ int      g_cnt[B_SZ];                       // per-row distinct-token counts
__device__ float2   g_part[2][B_SZ][L_SZ / 2];         // 4 MB partial sums

// ---------------------------------------------------------------------------
// K1: per-row dedupe -> compact byte-offset lists in global scratch.
// ---------------------------------------------------------------------------
__global__ __launch_bounds__(256) void bow_dedupe_kernel(
    const int* __restrict__ text)         // [T, B] int32
{
    __shared__ unsigned int bitmap[V_WORDS];  // 6.25 KB
    __shared__ int cnt;

    const int b   = blockIdx.x;
    const int tid = threadIdx.x;

    for (int i = tid; i < V_WORDS; i += 256) bitmap[i] = 0u;
    if (tid == 0) cnt = 0;
    __syncthreads();

    if (tid < T_TOK) {
        int v = text[(size_t)tid * B_SZ + b];
        if (v != PAD_TOK && (unsigned)v < (unsigned)V_SZ) {
            unsigned int bit = 1u << (v & 31);
            unsigned int old = atomicOr(&bitmap[v >> 5], bit);
            if (!(old & bit)) {
                int idx = atomicAdd(&cnt, 1);
                g_toks[b][idx] = (unsigned)v * (L_SZ * 2);   // byte offset into g_Wt_h
            }
        }
    }
    __syncthreads();
    if (tid == 0) g_cnt[b] = cnt;
}

// ---------------------------------------------------------------------------
// K2: tiled transpose + fp32->fp16 convert. W[L,V] f32 -> Wt[V,L] f16.
// ---------------------------------------------------------------------------
__global__ __launch_bounds__(256) void bow_transpose_f16_kernel(
    const float* __restrict__ W)
{
    __shared__ float tile[64][65];
    const int v0  = blockIdx.x * 64;
    const int l0  = blockIdx.y * 64;
    const int tid = threadIdx.x;

    {
        const int tx = tid & 15;
        const int ty = tid >> 4;
        const int v  = v0 + tx * 4;
        #pragma unroll
        for (int p = 0; p < 4; p++) {
            const int l = ty + p * 16;
            float4 val = make_float4(0.f, 0.f, 0.f, 0.f);
            if (v < V_SZ) {
                val = __ldcs((const float4*)(W + (size_t)(l0 + l) * V_SZ + v));
            }
            tile[l][tx * 4 + 0] = val.x;
            tile[l][tx * 4 + 1] = val.y;
            tile[l][tx * 4 + 2] = val.z;
            tile[l][tx * 4 + 3] = val.w;
        }
    }
    __syncthreads();

    {
        const int wx = tid & 7;
        const int wy = tid >> 3;
        #pragma unroll
        for (int p = 0; p < 2; p++) {
            const int vr = wy + p * 32;
            const int v  = v0 + vr;
            if (v < V_SZ) {
                const int lbase = wx * 8;
                __half2 h[4];
                #pragma unroll
                for (int k = 0; k < 4; k++) {
                    h[k] = __floats2half2_rn(tile[lbase + 2 * k][vr],
                                             tile[lbase + 2 * k + 1][vr]);
                }
                uint4 pkt;
                pkt.x = *(unsigned int*)&h[0];
                pkt.y = *(unsigned int*)&h[1];
                pkt.z = *(unsigned int*)&h[2];
                pkt.w = *(unsigned int*)&h[3];
                *(uint4*)(g_Wt_h + (size_t)v * L_SZ + l0 + lbase) = pkt;
            }
        }
    }
}

// ---------------------------------------------------------------------------
// K3: gather partial sums. Block (b, h): row b, token half h. 256 threads,
// thread t owns labels [2t, 2t+1] (one 4B half2 load/token). 8 accumulators.
// No bitmap smem -> 16384 warps -> full occupancy.
// ---------------------------------------------------------------------------
__global__ __launch_bounds__(256) void bow_gather_part_kernel(void)
{
    __shared__ unsigned offs[T_TOK];
    const int b   = blockIdx.x;
    const int h   = blockIdx.y;
    const int tid = threadIdx.x;

    const int n  = g_cnt[b];
    const int j0 = h ? (n >> 1) : 0;
    const int j1 = h ? n : (n >> 1);
    const int m  = j1 - j0;

    for (int i = tid; i < m; i += 256) offs[i] = g_toks[b][j0 + i];
    __syncthreads();

    const char* Wb = (const char*)g_Wt_h + (size_t)tid * 4;  // this thread's 2 labels

    float2 a0 = make_float2(0.f, 0.f);
    float2 a1 = make_float2(0.f, 0.f);
    float2 a2 = make_float2(0.f, 0.f);
    float2 a3 = make_float2(0.f, 0.f);
    float2 a4 = make_float2(0.f, 0.f);
    float2 a5 = make_float2(0.f, 0.f);
    float2 a6 = make_float2(0.f, 0.f);
    float2 a7 = make_float2(0.f, 0.f);

    int j = 0;
    for (; j + 8 <= m; j += 8) {
        unsigned int u0 = *(const unsigned int*)(Wb + offs[j + 0]);
        unsigned int u1 = *(const unsigned int*)(Wb + offs[j + 1]);
        unsigned int u2 = *(const unsigned int*)(Wb + offs[j + 2]);
        unsigned int u3 = *(const unsigned int*)(Wb + offs[j + 3]);
        unsigned int u4 = *(const unsigned int*)(Wb + offs[j + 4]);
        unsigned int u5 = *(const unsigned int*)(Wb + offs[j + 5]);
        unsigned int u6 = *(const unsigned int*)(Wb + offs[j + 6]);
        unsigned int u7 = *(const unsigned int*)(Wb + offs[j + 7]);
        float2 f;
        f = __half22float2(*(const __half2*)&u0); a0.x += f.x; a0.y += f.y;
        f = __half22float2(*(const __half2*)&u1); a1.x += f.x; a1.y += f.y;
        f = __half22float2(*(const __half2*)&u2); a2.x += f.x; a2.y += f.y;
        f = __half22float2(*(const __half2*)&u3); a3.x += f.x; a3.y += f.y;
        f = __half22float2(*(const __half2*)&u4); a4.x += f.x; a4.y += f.y;
        f = __half22float2(*(const __half2*)&u5); a5.x += f.x; a5.y += f.y;
        f = __half22float2(*(const __half2*)&u6); a6.x += f.x; a6.y += f.y;
        f = __half22float2(*(const __half2*)&u7); a7.x += f.x; a7.y += f.y;
    }
    for (; j < m; j++) {
        unsigned int u = *(const unsigned int*)(Wb + offs[j]);
        float2 f = __half22float2(*(const __half2*)&u);
        a0.x += f.x; a0.y += f.y;
    }

    float2 r;
    r.x = ((a0.x + a1.x) + (a2.x + a3.x)) + ((a4.x + a5.x) + (a6.x + a7.x));
    r.y = ((a0.y + a1.y) + (a2.y + a3.y)) + ((a4.y + a5.y) + (a6.y + a7.y));

    g_part[h][b][tid] = r;
}

// ---------------------------------------------------------------------------
// K4: combine. out[b][l] = bias[l] + part0[b][l] + part1[b][l]. float4 wide.
// ---------------------------------------------------------------------------
__global__ __launch_bounds__(128) void bow_combine_kernel(
    const float* __restrict__ bias,
    float* __restrict__ out)
{
    const int b   = blockIdx.x;
    const int tid = threadIdx.x;    // 128 threads x float4 = 512 labels

    float4 bs = ((const float4*)bias)[tid];
    float4 p0 = ((const float4*)g_part[0][b])[tid];
    float4 p1 = ((const float4*)g_part[1][b])[tid];
    float4 r;
    r.x = bs.x + p0.x + p1.x;
    r.y = bs.y + p0.y + p1.y;
    r.z = bs.z + p0.z + p1.z;
    r.w = bs.w + p0.w + p1.w;
    ((float4*)out)[(size_t)b * (L_SZ / 4) + tid] = r;
}

// ---------------------------------------------------------------------------
// Launch: dedupe -> transpose -> gather partials -> combine.
// Inputs: [0] text int32 [T,B], [1] W f32 [L,V], [2] b f32 [L].
// ---------------------------------------------------------------------------
extern "C" void kernel_launch(void* const* d_in, const int* in_sizes, int n_in,
                              void* d_out, int out_size) {
    const int*   text = (const int*)d_in[0];
    const float* W    = (const float*)d_in[1];
    const float* bias = (const float*)d_in[2];
    float*       out  = (float*)d_out;

    bow_dedupe_kernel<<<B_SZ, 256>>>(text);

    dim3 tgrid((V_SZ + 63) / 64, L_SZ / 64);   // 782 x 8
    bow_transpose_f16_kernel<<<tgrid, 256>>>(W);

    dim3 ggrid(B_SZ, 2);
    bow_gather_part_kernel<<<ggrid, 256>>>();

    bow_combine_kernel<<<B_SZ, 128>>>(bias, out);
}